// round 13
// baseline (speedup 1.0000x reference)
#include <cuda_runtime.h>
#include <cuda_bf16.h>
#include <cstdint>

// DynamicUpsamplingFilter: out[b,c,h,w] = sum_{dy,dx} x[b,c,h+dy-1,w+dx-1] * filters[b,dy*3+dx,h,w]
// x [4,128,180,320] f32, filters [4,9,180,320] f32, out [4,128,180,320] f32.
//
// R13: cp.async (LDGSTS) smem ring to decouple pipeline depth from the
// register file (R9-R12 all hit the RF wall at DRAM~58%). Per-warp 3-stage
// ring, look-ahead 2 channels; async copies hold no registers while in
// flight. Row layout per stage: [4 pad | 128 data | 4 pad] floats; lane L's
// float4 at 4+4L, left halo at 3+4L (lane L-1's .w or staged pad), right at
// 8+4L. Compute: 3 LDS.128 + 6 scalar LDS + 36 FMA; no shuffles/selects.
// Boundary handling: clamped offsets + zero-masked coefficients (covers
// mid-warp row crossings: garbage pads multiply zeroed coeffs).

#define B_ 4
#define C_ 128
#define H_ 180
#define W_ 320
#define CPB 32           // channels per block (grid.y = 4)
#define TPB 256
#define NW  (TPB / 32)   // 8 warps
#define STAGES 3
#define LOOK 2
#define ROWF 136         // floats per staged row
#define RB   (ROWF * 4)  // row bytes   = 544
#define STB  (3 * RB)    // stage bytes = 1632

__device__ __forceinline__ void cp16(uint32_t dst, const float* src) {
    asm volatile("cp.async.ca.shared.global [%0], [%1], 16;\n"
                 :: "r"(dst), "l"(src));
}
__device__ __forceinline__ void cp4(uint32_t dst, const float* src) {
    asm volatile("cp.async.ca.shared.global [%0], [%1], 4;\n"
                 :: "r"(dst), "l"(src));
}
__device__ __forceinline__ void cp_commit() {
    asm volatile("cp.async.commit_group;\n");
}
__device__ __forceinline__ void cp_wait1() {
    asm volatile("cp.async.wait_group 1;\n");
}

__global__ __launch_bounds__(TPB, 3)
void duf_kernel(const float* __restrict__ x,
                const float* __restrict__ filters,
                float* __restrict__ out)
{
    __shared__ float sbuf[NW][STAGES][3][ROWF];   // 39168 bytes

    const int HW = H_ * W_;
    int tid = blockIdx.x * TPB + threadIdx.x;
    const int WQ = W_ / 4;             // 80 pixel-quads per row
    int wq = tid % WQ;
    int t2 = tid / WQ;
    int h  = t2 % H_;
    int b  = t2 / H_;
    int w  = wq * 4;
    int lane = threadIdx.x & 31;
    int wid  = threadIdx.x >> 5;

    int c0 = blockIdx.y * CPB;

    // ---- 9 filter float4s (tap i, pixels w..w+3) ----
    const float* fb = filters + ((size_t)b * 9) * HW + (size_t)h * W_ + w;
    float4 f[9];
#pragma unroll
    for (int i = 0; i < 9; i++)
        f[i] = __ldg((const float4*)(fb + (size_t)i * HW));

    // ---- boundary masks folded into coefficients ----
    if (h == 0) {
        f[0] = make_float4(0,0,0,0);
        f[1] = make_float4(0,0,0,0);
        f[2] = make_float4(0,0,0,0);
    }
    if (h == H_ - 1) {
        f[6] = make_float4(0,0,0,0);
        f[7] = make_float4(0,0,0,0);
        f[8] = make_float4(0,0,0,0);
    }
    if (w == 0) {                  // pixel0 left taps (kills pad/crossing garbage)
        f[0].x = 0.f; f[3].x = 0.f; f[6].x = 0.f;
    }
    if (w + 4 == W_) {             // pixel3 right taps (ditto)
        f[2].w = 0.f; f[5].w = 0.f; f[8].w = 0.f;
    }

    // clamped offsets (clamped values hit zeroed coefficients)
    int hm = (h > 0)      ? h - 1 : 0;
    int hp = (h < H_ - 1) ? h + 1 : h;
    int wl = (w > 0)      ? w - 1 : 0;        // scalar x(w-1)
    int wr = (w + 4 < W_) ? w + 4 : W_ - 1;   // scalar x(w+4)

    const bool ld_l = (lane == 0);
    const bool ld_r = (lane == 31);

    const float* base = x + ((size_t)(b * C_ + c0)) * HW;
    const float* pm = base + (size_t)hm * W_;   // load-side pointers
    const float* p0 = base + (size_t)h  * W_;
    const float* pp = base + (size_t)hp * W_;
    float* po = out + (((size_t)(b * C_ + c0)) * H_ + h) * (size_t)W_ + w;

    uint32_t swarp = (uint32_t)__cvta_generic_to_shared(&sbuf[wid][0][0][0]);
    uint32_t dmain = 16 + 16 * lane;           // byte offset of lane's float4

#define STAGE(S)                                                        \
    {                                                                   \
        uint32_t d = swarp + (S) * STB;                                 \
        cp16(d + dmain,          pm + w);                               \
        cp16(d + RB + dmain,     p0 + w);                               \
        cp16(d + 2 * RB + dmain, pp + w);                               \
        if (ld_l) {                                                     \
            cp4(d + 12,          pm + wl);                              \
            cp4(d + RB + 12,     p0 + wl);                              \
            cp4(d + 2 * RB + 12, pp + wl);                              \
        }                                                               \
        if (ld_r) {                                                     \
            cp4(d + 528,          pm + wr);                             \
            cp4(d + RB + 528,     p0 + wr);                             \
            cp4(d + 2 * RB + 528, pp + wr);                             \
        }                                                               \
        pm += HW; p0 += HW; pp += HW;                                   \
    }

    // ---- prologue: stage channels 0,1 into stages 0,1 ----
    STAGE(0); cp_commit();
    STAGE(1); cp_commit();

    int sc = 0;            // compute stage
    int sl = 2;            // load stage
    int idx = 4 + 4 * lane;

#pragma unroll 1
    for (int c = 0; c < CPB; ++c) {
        cp_wait1();        // oldest group (channel c) complete
        __syncwarp();

        const float* rm = &sbuf[wid][sc][0][0];
        const float* r0 = &sbuf[wid][sc][1][0];
        const float* rp = &sbuf[wid][sc][2][0];

        float4 vm = *(const float4*)(rm + idx);
        float  ml = rm[idx - 1];
        float  mr = rm[idx + 4];
        float4 v0 = *(const float4*)(r0 + idx);
        float  zl = r0[idx - 1];
        float  zr = r0[idx + 4];
        float4 vp = *(const float4*)(rp + idx);
        float  pl = rp[idx - 1];
        float  pr = rp[idx + 4];

        float4 acc;
        acc.x = f[0].x*ml   + f[1].x*vm.x + f[2].x*vm.y
              + f[3].x*zl   + f[4].x*v0.x + f[5].x*v0.y
              + f[6].x*pl   + f[7].x*vp.x + f[8].x*vp.y;
        acc.y = f[0].y*vm.x + f[1].y*vm.y + f[2].y*vm.z
              + f[3].y*v0.x + f[4].y*v0.y + f[5].y*v0.z
              + f[6].y*vp.x + f[7].y*vp.y + f[8].y*vp.z;
        acc.z = f[0].z*vm.y + f[1].z*vm.z + f[2].z*vm.w
              + f[3].z*v0.y + f[4].z*v0.z + f[5].z*v0.w
              + f[6].z*vp.y + f[7].z*vp.z + f[8].z*vp.w;
        acc.w = f[0].w*vm.z + f[1].w*vm.w + f[2].w*mr
              + f[3].w*v0.z + f[4].w*v0.w + f[5].w*zr
              + f[6].w*vp.z + f[7].w*vp.w + f[8].w*pr;

        *((float4*)po) = acc;
        po += HW;

        if (c + LOOK < CPB) STAGE(sl);
        cp_commit();       // empty group at tail keeps the count aligned

        sc = (sc == STAGES - 1) ? 0 : sc + 1;
        sl = (sl == STAGES - 1) ? 0 : sl + 1;
    }
#undef STAGE
}

extern "C" void kernel_launch(void* const* d_in, const int* in_sizes, int n_in,
                              void* d_out, int out_size)
{
    const float* x       = (const float*)d_in[0];
    const float* filters = (const float*)d_in[1];
    float* out           = (float*)d_out;

    int spatial_threads = B_ * H_ * (W_ / 4);     // 57600
    dim3 grid(spatial_threads / TPB, C_ / CPB);   // (225, 4) = 900 blocks
    duf_kernel<<<grid, TPB>>>(x, filters, out);
}

// round 14
// speedup vs baseline: 1.2140x; 1.2140x over previous
#include <cuda_runtime.h>
#include <cuda_bf16.h>
#include <cstdint>

// DynamicUpsamplingFilter: out[b,c,h,w] = sum_{dy,dx} x[b,c,h+dy-1,w+dx-1] * filters[b,dy*3+dx,h,w]
// x [4,128,180,320] f32, filters [4,9,180,320] f32, out [4,128,180,320] f32.
//
// R14: TMA bulk-copy slab kernel. Register pipelines hit the RF wall
// (DRAM ~58%, R9-R12); per-thread cp.async hit the L1 wall (80%, R13).
// cp.async.bulk bypasses both: L2->smem direct, zero registers held.
// Block = (b, 4 output rows x full W, 32 channels), 320 threads. Per channel
// ONE bulk copy of 6 contiguous input rows (7680B) into a 4-stage smem ring
// with mbarrier expect_tx. 4 stages x 7680B x 2 CTA = ~480 lines in flight
// per SM. Compute: 3 LDS.128 + shuffles + 36 FMA; boundary handling via
// clamped slab offsets x zero-masked coefficients (incl. mid-warp row
// crossings: garbage shfl values hit zeroed coeffs).

#define B_ 4
#define C_ 128
#define H_ 180
#define W_ 320
#define CPB 32
#define TPB 320
#define RT  4              // output rows per block tile
#define SLAB 6             // staged input rows (contiguous in gmem)
#define STAGES 4
#define SLAB_BYTES (SLAB * W_ * 4)   // 7680

__device__ __forceinline__ uint32_t s2u(const void* p) {
    return (uint32_t)__cvta_generic_to_shared(p);
}
__device__ __forceinline__ void mbar_init(uint32_t a, uint32_t cnt) {
    asm volatile("mbarrier.init.shared.b64 [%0], %1;" :: "r"(a), "r"(cnt) : "memory");
}
__device__ __forceinline__ void mbar_expect_tx(uint32_t a, uint32_t bytes) {
    asm volatile("mbarrier.arrive.expect_tx.shared.b64 _, [%0], %1;"
                 :: "r"(a), "r"(bytes) : "memory");
}
__device__ __forceinline__ void bulk_g2s(uint32_t dst, const float* src,
                                         uint32_t bytes, uint32_t mb) {
    asm volatile("cp.async.bulk.shared::cta.global.mbarrier::complete_tx::bytes "
                 "[%0], [%1], %2, [%3];"
                 :: "r"(dst), "l"(src), "r"(bytes), "r"(mb) : "memory");
}
__device__ __forceinline__ void mbar_wait(uint32_t a, uint32_t parity) {
    uint32_t done;
    asm volatile(
        "{\n\t.reg .pred p;\n\t"
        "mbarrier.try_wait.parity.acquire.cta.shared::cta.b64 p, [%1], %2;\n\t"
        "selp.b32 %0, 1, 0, p;\n\t}"
        : "=r"(done) : "r"(a), "r"(parity) : "memory");
    if (!done) {
        asm volatile(
            "{\n\t.reg .pred P1;\n\t"
            "WL_%=:\n\t"
            "mbarrier.try_wait.parity.acquire.cta.shared::cta.b64 P1, [%0], %1, 0x989680;\n\t"
            "@P1 bra.uni WD_%=;\n\t"
            "bra.uni WL_%=;\n\t"
            "WD_%=:\n\t}"
            :: "r"(a), "r"(parity) : "memory");
    }
}

__global__ __launch_bounds__(TPB, 2)
void duf_kernel(const float* __restrict__ x,
                const float* __restrict__ filters,
                float* __restrict__ out)
{
    __shared__ alignas(128) float slab[STAGES][SLAB][W_];   // 30720 B
    __shared__ uint64_t mbar[STAGES];

    const int HW = H_ * W_;
    int tid  = threadIdx.x;
    int lane = tid & 31;

    int rt = blockIdx.x % (H_ / RT);      // 45 row tiles
    int b  = blockIdx.x / (H_ / RT);
    int h0 = rt * RT;
    int r  = tid / (W_ / 4);              // output row within tile, 0..3
    int wq = tid % (W_ / 4);
    int w  = wq * 4;
    int h  = h0 + r;
    int c0 = blockIdx.y * CPB;

    // ---- mbarrier init + prologue bulk copies (channels 0..3) ----
    int slab_start = h0 - 1;
    if (slab_start < 0) slab_start = 0;
    if (slab_start > H_ - SLAB) slab_start = H_ - SLAB;

    const float* gsrc = x + ((size_t)(b * C_ + c0) * H_ + slab_start) * W_;

    if (tid == 0) {
#pragma unroll
        for (int s = 0; s < STAGES; s++)
            mbar_init(s2u(&mbar[s]), 1);
    }
    __syncthreads();
    if (tid == 0) {
#pragma unroll
        for (int s = 0; s < STAGES; s++) {
            mbar_expect_tx(s2u(&mbar[s]), SLAB_BYTES);
            bulk_g2s(s2u(&slab[s][0][0]), gsrc + (size_t)s * HW,
                     SLAB_BYTES, s2u(&mbar[s]));
        }
    }

    // ---- filters: 9 float4 taps, loaded while TMAs fly ----
    const float* fb = filters + ((size_t)b * 9) * HW + (size_t)h * W_ + w;
    float4 f[9];
#pragma unroll
    for (int i = 0; i < 9; i++)
        f[i] = __ldg((const float4*)(fb + (size_t)i * HW));

    // boundary masks folded into coefficients
    if (h == 0) {
        f[0] = make_float4(0,0,0,0);
        f[1] = make_float4(0,0,0,0);
        f[2] = make_float4(0,0,0,0);
    }
    if (h == H_ - 1) {
        f[6] = make_float4(0,0,0,0);
        f[7] = make_float4(0,0,0,0);
        f[8] = make_float4(0,0,0,0);
    }
    if (w == 0) {                 // also neutralizes row-cross shfl garbage
        f[0].x = 0.f; f[3].x = 0.f; f[6].x = 0.f;
    }
    if (w + 4 == W_) {
        f[2].w = 0.f; f[5].w = 0.f; f[8].w = 0.f;
    }

    // smem row indices (clamped rows hit zeroed coefficients)
    int rm_i = h - 1 - slab_start; if (rm_i < 0) rm_i = 0;
    int r0_i = h - slab_start;
    int rp_i = h + 1 - slab_start; if (rp_i > SLAB - 1) rp_i = SLAB - 1;

    int wl = (w > 0)      ? w - 1 : 0;
    int wr = (w + 4 < W_) ? w + 4 : W_ - 1;
    const bool ld_l = (lane == 0);
    const bool ld_r = (lane == 31);

    float* po = out + (((size_t)(b * C_ + c0)) * H_ + h) * (size_t)W_ + w;

#pragma unroll 1
    for (int c = 0; c < CPB; ++c) {
        int s = c & (STAGES - 1);
        mbar_wait(s2u(&mbar[s]), (c >> 2) & 1);

        const float* rm = &slab[s][rm_i][0];
        const float* r0 = &slab[s][r0_i][0];
        const float* rp = &slab[s][rp_i][0];

        float4 vm = *(const float4*)(rm + w);
        float4 v0 = *(const float4*)(r0 + w);
        float4 vp = *(const float4*)(rp + w);

        // halos: neighbor-lane shuffles; warp-edge lanes read smem directly
        float sml = __shfl_up_sync(0xffffffffu,  vm.w, 1);
        float s0l = __shfl_up_sync(0xffffffffu,  v0.w, 1);
        float spl = __shfl_up_sync(0xffffffffu,  vp.w, 1);
        float smr = __shfl_down_sync(0xffffffffu, vm.x, 1);
        float s0r = __shfl_down_sync(0xffffffffu, v0.x, 1);
        float spr = __shfl_down_sync(0xffffffffu, vp.x, 1);
        float vml = ld_l ? rm[wl] : sml;
        float v0l = ld_l ? r0[wl] : s0l;
        float vpl = ld_l ? rp[wl] : spl;
        float vmr = ld_r ? rm[wr] : smr;
        float v0r = ld_r ? r0[wr] : s0r;
        float vpr = ld_r ? rp[wr] : spr;

        float4 acc;
        acc.x = f[0].x*vml  + f[1].x*vm.x + f[2].x*vm.y
              + f[3].x*v0l  + f[4].x*v0.x + f[5].x*v0.y
              + f[6].x*vpl  + f[7].x*vp.x + f[8].x*vp.y;
        acc.y = f[0].y*vm.x + f[1].y*vm.y + f[2].y*vm.z
              + f[3].y*v0.x + f[4].y*v0.y + f[5].y*v0.z
              + f[6].y*vp.x + f[7].y*vp.y + f[8].y*vp.z;
        acc.z = f[0].z*vm.y + f[1].z*vm.z + f[2].z*vm.w
              + f[3].z*v0.y + f[4].z*v0.z + f[5].z*v0.w
              + f[6].z*vp.y + f[7].z*vp.z + f[8].z*vp.w;
        acc.w = f[0].w*vm.z + f[1].w*vm.w + f[2].w*vmr
              + f[3].w*v0.z + f[4].w*v0.w + f[5].w*v0r
              + f[6].w*vp.z + f[7].w*vp.w + f[8].w*vpr;

        *((float4*)po) = acc;
        po += HW;

        __syncthreads();       // all reads of stage s done
        if (tid == 0 && c + STAGES < CPB) {
            mbar_expect_tx(s2u(&mbar[s]), SLAB_BYTES);
            bulk_g2s(s2u(&slab[s][0][0]), gsrc + (size_t)(c + STAGES) * HW,
                     SLAB_BYTES, s2u(&mbar[s]));
        }
    }
}

extern "C" void kernel_launch(void* const* d_in, const int* in_sizes, int n_in,
                              void* d_out, int out_size)
{
    const float* x       = (const float*)d_in[0];
    const float* filters = (const float*)d_in[1];
    float* out           = (float*)d_out;

    dim3 grid(B_ * (H_ / RT), C_ / CPB);    // (180, 4) = 720 blocks
    duf_kernel<<<grid, TPB>>>(x, filters, out);
}

// round 15
// speedup vs baseline: 1.2604x; 1.0382x over previous
#include <cuda_runtime.h>
#include <cuda_bf16.h>
#include <cstdint>

// DynamicUpsamplingFilter: out[b,c,h,w] = sum_{dy,dx} x[b,c,h+dy-1,w+dx-1] * filters[b,dy*3+dx,h,w]
// x [4,128,180,320] f32, filters [4,9,180,320] f32, out [4,128,180,320] f32.
//
// R15: R14's TMA slab kernel with sync machinery amortized 2x. Two channels
// per pipeline stage (one mbarrier transaction = 2 bulk copies, 15360B), two
// stages -> 16 loop iterations instead of 32: half the mbar waits and
// __syncthreads per output. While computing one stage, the other stage's 2
// channels (240 lines across 2 CTAs/SM) stream via TMA (L2->smem, no L1, no
// registers held). Compute: LDS.128 + shuffles + 36 FMA per channel.
// Boundaries: clamped offsets x zero-masked coefficients (covers mid-warp
// row crossings).

#define B_ 4
#define C_ 128
#define H_ 180
#define W_ 320
#define CPB 32
#define TPB 320
#define RT  4              // output rows per block tile
#define SLAB 6             // staged input rows per channel (contiguous)
#define CH  2              // channels per stage
#define STAGES 2
#define SLAB_BYTES (SLAB * W_ * 4)          // 7680 per channel
#define STAGE_BYTES (CH * SLAB_BYTES)       // 15360 per stage
#define NIT (CPB / CH)                      // 16 iterations

__device__ __forceinline__ uint32_t s2u(const void* p) {
    return (uint32_t)__cvta_generic_to_shared(p);
}
__device__ __forceinline__ void mbar_init(uint32_t a, uint32_t cnt) {
    asm volatile("mbarrier.init.shared.b64 [%0], %1;" :: "r"(a), "r"(cnt) : "memory");
}
__device__ __forceinline__ void mbar_expect_tx(uint32_t a, uint32_t bytes) {
    asm volatile("mbarrier.arrive.expect_tx.shared.b64 _, [%0], %1;"
                 :: "r"(a), "r"(bytes) : "memory");
}
__device__ __forceinline__ void bulk_g2s(uint32_t dst, const float* src,
                                         uint32_t bytes, uint32_t mb) {
    asm volatile("cp.async.bulk.shared::cta.global.mbarrier::complete_tx::bytes "
                 "[%0], [%1], %2, [%3];"
                 :: "r"(dst), "l"(src), "r"(bytes), "r"(mb) : "memory");
}
__device__ __forceinline__ void mbar_wait(uint32_t a, uint32_t parity) {
    uint32_t done;
    asm volatile(
        "{\n\t.reg .pred p;\n\t"
        "mbarrier.try_wait.parity.acquire.cta.shared::cta.b64 p, [%1], %2;\n\t"
        "selp.b32 %0, 1, 0, p;\n\t}"
        : "=r"(done) : "r"(a), "r"(parity) : "memory");
    if (!done) {
        asm volatile(
            "{\n\t.reg .pred P1;\n\t"
            "WL_%=:\n\t"
            "mbarrier.try_wait.parity.acquire.cta.shared::cta.b64 P1, [%0], %1, 0x989680;\n\t"
            "@P1 bra.uni WD_%=;\n\t"
            "bra.uni WL_%=;\n\t"
            "WD_%=:\n\t}"
            :: "r"(a), "r"(parity) : "memory");
    }
}

__global__ __launch_bounds__(TPB, 2)
void duf_kernel(const float* __restrict__ x,
                const float* __restrict__ filters,
                float* __restrict__ out)
{
    __shared__ alignas(128) float slab[STAGES][CH][SLAB][W_];   // 30720 B
    __shared__ uint64_t mbar[STAGES];

    const int HW = H_ * W_;
    int tid  = threadIdx.x;
    int lane = tid & 31;

    int rt = blockIdx.x % (H_ / RT);      // 45 row tiles
    int b  = blockIdx.x / (H_ / RT);
    int h0 = rt * RT;
    int r  = tid / (W_ / 4);              // output row within tile, 0..3
    int wq = tid % (W_ / 4);
    int w  = wq * 4;
    int h  = h0 + r;
    int c0 = blockIdx.y * CPB;

    int slab_start = h0 - 1;
    if (slab_start < 0) slab_start = 0;
    if (slab_start > H_ - SLAB) slab_start = H_ - SLAB;

    const float* gsrc = x + ((size_t)(b * C_ + c0) * H_ + slab_start) * W_;

    if (tid == 0) {
#pragma unroll
        for (int s = 0; s < STAGES; s++)
            mbar_init(s2u(&mbar[s]), 1);
    }
    __syncthreads();
    // prologue: stage 0 <- channels 0,1 ; stage 1 <- channels 2,3
    if (tid == 0) {
#pragma unroll
        for (int s = 0; s < STAGES; s++) {
            mbar_expect_tx(s2u(&mbar[s]), STAGE_BYTES);
#pragma unroll
            for (int k = 0; k < CH; k++)
                bulk_g2s(s2u(&slab[s][k][0][0]),
                         gsrc + (size_t)(s * CH + k) * HW,
                         SLAB_BYTES, s2u(&mbar[s]));
        }
    }

    // ---- filters: 9 float4 taps, loaded while TMAs fly ----
    const float* fb = filters + ((size_t)b * 9) * HW + (size_t)h * W_ + w;
    float4 f[9];
#pragma unroll
    for (int i = 0; i < 9; i++)
        f[i] = __ldg((const float4*)(fb + (size_t)i * HW));

    if (h == 0) {
        f[0] = make_float4(0,0,0,0);
        f[1] = make_float4(0,0,0,0);
        f[2] = make_float4(0,0,0,0);
    }
    if (h == H_ - 1) {
        f[6] = make_float4(0,0,0,0);
        f[7] = make_float4(0,0,0,0);
        f[8] = make_float4(0,0,0,0);
    }
    if (w == 0) {                 // also neutralizes row-cross shfl garbage
        f[0].x = 0.f; f[3].x = 0.f; f[6].x = 0.f;
    }
    if (w + 4 == W_) {
        f[2].w = 0.f; f[5].w = 0.f; f[8].w = 0.f;
    }

    // smem row indices (clamped rows hit zeroed coefficients)
    int rm_i = h - 1 - slab_start; if (rm_i < 0) rm_i = 0;
    int r0_i = h - slab_start;
    int rp_i = h + 1 - slab_start; if (rp_i > SLAB - 1) rp_i = SLAB - 1;

    int wl = (w > 0)      ? w - 1 : 0;
    int wr = (w + 4 < W_) ? w + 4 : W_ - 1;
    const bool ld_l = (lane == 0);
    const bool ld_r = (lane == 31);

    float* po = out + (((size_t)(b * C_ + c0)) * H_ + h) * (size_t)W_ + w;

#pragma unroll 1
    for (int i = 0; i < NIT; ++i) {
        int s = i & 1;
        mbar_wait(s2u(&mbar[s]), (i >> 1) & 1);

#pragma unroll
        for (int k = 0; k < CH; k++) {
            const float* rm = &slab[s][k][rm_i][0];
            const float* r0 = &slab[s][k][r0_i][0];
            const float* rp = &slab[s][k][rp_i][0];

            float4 vm = *(const float4*)(rm + w);
            float4 v0 = *(const float4*)(r0 + w);
            float4 vp = *(const float4*)(rp + w);

            float sml = __shfl_up_sync(0xffffffffu,  vm.w, 1);
            float s0l = __shfl_up_sync(0xffffffffu,  v0.w, 1);
            float spl = __shfl_up_sync(0xffffffffu,  vp.w, 1);
            float smr = __shfl_down_sync(0xffffffffu, vm.x, 1);
            float s0r = __shfl_down_sync(0xffffffffu, v0.x, 1);
            float spr = __shfl_down_sync(0xffffffffu, vp.x, 1);
            float vml = ld_l ? rm[wl] : sml;
            float v0l = ld_l ? r0[wl] : s0l;
            float vpl = ld_l ? rp[wl] : spl;
            float vmr = ld_r ? rm[wr] : smr;
            float v0r = ld_r ? r0[wr] : s0r;
            float vpr = ld_r ? rp[wr] : spr;

            float4 acc;
            acc.x = f[0].x*vml  + f[1].x*vm.x + f[2].x*vm.y
                  + f[3].x*v0l  + f[4].x*v0.x + f[5].x*v0.y
                  + f[6].x*vpl  + f[7].x*vp.x + f[8].x*vp.y;
            acc.y = f[0].y*vm.x + f[1].y*vm.y + f[2].y*vm.z
                  + f[3].y*v0.x + f[4].y*v0.y + f[5].y*v0.z
                  + f[6].y*vp.x + f[7].y*vp.y + f[8].y*vp.z;
            acc.z = f[0].z*vm.y + f[1].z*vm.z + f[2].z*vm.w
                  + f[3].z*v0.y + f[4].z*v0.z + f[5].z*v0.w
                  + f[6].z*vp.y + f[7].z*vp.z + f[8].z*vp.w;
            acc.w = f[0].w*vm.z + f[1].w*vm.w + f[2].w*vmr
                  + f[3].w*v0.z + f[4].w*v0.w + f[5].w*v0r
                  + f[6].w*vp.z + f[7].w*vp.w + f[8].w*vpr;

            *((float4*)po) = acc;
            po += HW;
        }

        __syncthreads();       // all reads of stage s done
        if (tid == 0 && i + STAGES < NIT) {
            mbar_expect_tx(s2u(&mbar[s]), STAGE_BYTES);
#pragma unroll
            for (int k = 0; k < CH; k++)
                bulk_g2s(s2u(&slab[s][k][0][0]),
                         gsrc + (size_t)((i + STAGES) * CH + k) * HW,
                         SLAB_BYTES, s2u(&mbar[s]));
        }
    }
}

extern "C" void kernel_launch(void* const* d_in, const int* in_sizes, int n_in,
                              void* d_out, int out_size)
{
    const float* x       = (const float*)d_in[0];
    const float* filters = (const float*)d_in[1];
    float* out           = (float*)d_out;

    dim3 grid(B_ * (H_ / RT), C_ / CPB);    // (180, 4) = 720 blocks
    duf_kernel<<<grid, TPB>>>(x, filters, out);
}